// round 8
// baseline (speedup 1.0000x reference)
#include <cuda_runtime.h>

#define N    4096
#define K    10          // fused Jacobi steps per pass
#define BX   256         // tile width
#define BY   128         // tile height
#define HX   12          // x halo (>= K, multiple of 4 for alignment)
#define HY   10          // y halo (= K)
#define VX   232         // valid output width
#define VY   108         // valid output height
#define TXN  18          // ceil(4096/232)
#define TYN  38          // ceil(4096/108)
#define NTH  512
#define NW   16          // warps per CTA
#define R    8           // rows per warp (NW * R == BY)

#define SCALE 0x1p-20f   // 0.25^K, exact power of two

// Scratch ping-pong buffer (allocation-free rule: __device__ global).
__device__ float g_buf[(size_t)N * N];

// dynamic smem exchange: [parity][top=0/bot=1][warp][BX floats] = 64 KB
#define EX_STRIDE  BX
#define EX_SIDE    (NW * EX_STRIDE)
#define EX_PAR     (2 * EX_SIDE)
#define SMEM_BYTES (2 * EX_PAR * (int)sizeof(float))

template<bool EDGE>
__device__ __forceinline__ void run_steps(float4 (&uL)[R], float4 (&uH)[R],
                                          float* ex, int warp, int lane,
                                          int gx0, int gy0, int ybase) {
    float4 mxL = make_float4(1.f,1.f,1.f,1.f), mxH = mxL;
    if (EDGE) {
        int g = gx0 + lane * 8;
        #pragma unroll
        for (int e = 0; e < 4; e++) {
            (&mxL.x)[e] = (g + e     >= 1 && g + e     <= N - 2) ? 1.f : 0.f;
            (&mxH.x)[e] = (g + e + 4 >= 1 && g + e + 4 <= N - 2) ? 1.f : 0.f;
        }
    }
    const int lx = lane * 8;

    #pragma unroll 2
    for (int s = 0; s < K; s++) {
        float* exP = ex + (s & 1) * EX_PAR;
        float* topP = exP + 0 * EX_SIDE + warp * EX_STRIDE + lx;
        float* botP = exP + 1 * EX_SIDE + warp * EX_STRIDE + lx;
        // publish own (old) boundary rows
        *(float4*)(topP)     = uL[0];     *(float4*)(topP + 4) = uH[0];
        *(float4*)(botP)     = uL[R-1];   *(float4*)(botP + 4) = uH[R-1];
        __syncthreads();

        float4 aL = make_float4(0,0,0,0), aH = aL;     // row above my block
        if (warp > 0) {
            const float* p = exP + 1 * EX_SIDE + (warp - 1) * EX_STRIDE + lx;
            aL = *(const float4*)p; aH = *(const float4*)(p + 4);
        }
        float4 bL = make_float4(0,0,0,0), bH = bL;     // row below my block
        if (warp < NW - 1) {
            const float* p = exP + 0 * EX_SIDE + (warp + 1) * EX_STRIDE + lx;
            bL = *(const float4*)p; bH = *(const float4*)(p + 4);
        }

        #pragma unroll
        for (int r = 0; r < R; r++) {
            float4 cL = uL[r], cH = uH[r];
            float4 dL = (r < R - 1) ? uL[r + 1] : bL;
            float4 dH = (r < R - 1) ? uH[r + 1] : bH;
            float lf = __shfl_up_sync(0xffffffffu, cH.w, 1);
            float rt = __shfl_down_sync(0xffffffffu, cL.x, 1);

            // UNSCALED sum; 0.25^K applied once in epilogue (bit-exact)
            float4 nL, nH;
            nL.x = (lf   + cL.y) + (aL.x + dL.x);
            nL.y = (cL.x + cL.z) + (aL.y + dL.y);
            nL.z = (cL.y + cL.w) + (aL.z + dL.z);
            nL.w = (cL.z + cH.x) + (aL.w + dL.w);
            nH.x = (cL.w + cH.y) + (aH.x + dH.x);
            nH.y = (cH.x + cH.z) + (aH.y + dH.y);
            nH.z = (cH.y + cH.w) + (aH.z + dH.z);
            nH.w = (cH.z + rt  ) + (aH.w + dH.w);

            if (EDGE) {
                int gy = gy0 + ybase + r;
                float my = (gy >= 1 && gy <= N - 2) ? 1.f : 0.f;
                nL.x *= my * mxL.x; nL.y *= my * mxL.y;
                nL.z *= my * mxL.z; nL.w *= my * mxL.w;
                nH.x *= my * mxH.x; nH.y *= my * mxH.y;
                nH.z *= my * mxH.z; nH.w *= my * mxH.w;
            }

            uL[r] = nL; uH[r] = nH;
            aL = cL; aH = cH;      // old values feed the next row
        }
    }
}

__device__ __forceinline__ void store_center(float4 (&uL)[R], float4 (&uH)[R],
                                             float* __restrict__ out,
                                             int warp, int lane,
                                             int gx0, int gy0, int ybase) {
    const int lx = lane * 8;
    #pragma unroll
    for (int r = 0; r < R; r++) {
        int ty = ybase + r;
        if (ty < HY || ty > BY - 1 - HY) continue;       // valid rows [10,117]
        int gy = gy0 + ty;
        if (gy >= N) continue;
        float* rowp = out + (size_t)gy * N;
        #pragma unroll
        for (int h = 0; h < 2; h++) {
            int c0 = lx + 4 * h;
            if (c0 < HX || c0 + 3 > HX + VX - 1) continue;  // valid cols [12,243]
            int gx = gx0 + c0;
            float4 v = (h == 0) ? uL[r] : uH[r];
            v.x *= SCALE; v.y *= SCALE; v.z *= SCALE; v.w *= SCALE;
            if (gx + 3 < N) {
                *(float4*)&rowp[gx] = v;
            } else {
                #pragma unroll
                for (int e = 0; e < 4; e++)
                    if (gx + e < N) rowp[gx + e] = (&v.x)[e];
            }
        }
    }
}

// ---- pass 0: compute x0 = exp(-50((X-.5)^2+(Y-.5)^2)) in-register, then K steps ----
__global__ __launch_bounds__(NTH, 1)
void jacobi_first(const float* __restrict__ X, const float* __restrict__ Y,
                  float* __restrict__ out) {
    extern __shared__ float ex[];

    const int tid   = threadIdx.x;
    const int lane  = tid & 31;
    const int warp  = tid >> 5;
    const int lx    = lane * 8;
    const int gx0   = blockIdx.x * VX - HX;
    const int gy0   = blockIdx.y * VY - HY;
    const int ybase = warp * R;

    const bool interior =
        (gx0 >= 1) && (gx0 + BX - 1 <= N - 2) &&
        (gy0 >= 1) && (gy0 + BY - 1 <= N - 2);

    float4 uL[R], uH[R];

    if (interior) {
        #pragma unroll
        for (int r = 0; r < R; r++) {
            size_t base = (size_t)(gy0 + ybase + r) * N + gx0 + lx;
            #pragma unroll
            for (int e = 0; e < 8; e++) {
                float dx = X[base + e] - 0.5f;
                float dy = Y[base + e] - 0.5f;
                float v  = __expf(-50.0f * (dx * dx + dy * dy));
                if (e < 4) (&uL[r].x)[e] = v; else (&uH[r].x)[e - 4] = v;
            }
        }
    } else {
        #pragma unroll
        for (int r = 0; r < R; r++) {
            int gy = gy0 + ybase + r;
            #pragma unroll
            for (int e = 0; e < 8; e++) {
                float v = 0.f;
                int g = gx0 + lx + e;
                if (gy >= 0 && gy < N && g >= 0 && g < N) {
                    size_t idx = (size_t)gy * N + g;
                    float dx = X[idx] - 0.5f;
                    float dy = Y[idx] - 0.5f;
                    v = __expf(-50.0f * (dx * dx + dy * dy));
                }
                if (e < 4) (&uL[r].x)[e] = v; else (&uH[r].x)[e - 4] = v;
            }
        }
    }

    if (interior) run_steps<false>(uL, uH, ex, warp, lane, gx0, gy0, ybase);
    else          run_steps<true >(uL, uH, ex, warp, lane, gx0, gy0, ybase);

    store_center(uL, uH, out, warp, lane, gx0, gy0, ybase);
}

// ---- passes 1..9: load prev state, K steps ----
__global__ __launch_bounds__(NTH, 1)
void jacobi_pass(const float* __restrict__ in, float* __restrict__ out) {
    extern __shared__ float ex[];

    const int tid   = threadIdx.x;
    const int lane  = tid & 31;
    const int warp  = tid >> 5;
    const int lx    = lane * 8;
    const int gx0   = blockIdx.x * VX - HX;
    const int gy0   = blockIdx.y * VY - HY;
    const int ybase = warp * R;

    const bool interior =
        (gx0 >= 1) && (gx0 + BX - 1 <= N - 2) &&
        (gy0 >= 1) && (gy0 + BY - 1 <= N - 2);

    float4 uL[R], uH[R];

    if (interior) {
        #pragma unroll
        for (int r = 0; r < R; r++) {
            const float* p = in + (size_t)(gy0 + ybase + r) * N + gx0 + lx;
            uL[r] = *(const float4*)p;
            uH[r] = *(const float4*)(p + 4);
        }
    } else {
        #pragma unroll
        for (int r = 0; r < R; r++) {
            int gy = gy0 + ybase + r;
            #pragma unroll
            for (int e = 0; e < 8; e++) {
                float v = 0.f;
                int g = gx0 + lx + e;
                if (gy >= 0 && gy < N && g >= 0 && g < N)
                    v = in[(size_t)gy * N + g];
                if (e < 4) (&uL[r].x)[e] = v; else (&uH[r].x)[e - 4] = v;
            }
        }
    }

    if (interior) run_steps<false>(uL, uH, ex, warp, lane, gx0, gy0, ybase);
    else          run_steps<true >(uL, uH, ex, warp, lane, gx0, gy0, ybase);

    store_center(uL, uH, out, warp, lane, gx0, gy0, ybase);
}

extern "C" void kernel_launch(void* const* d_in, const int* in_sizes, int n_in,
                              void* d_out, int out_size) {
    const float* X = (const float*)d_in[0];
    const float* Y = (const float*)d_in[1];
    float* A = (float*)d_out;
    float* B;
    cudaGetSymbolAddress((void**)&B, g_buf);

    cudaFuncSetAttribute(jacobi_first,
                         cudaFuncAttributeMaxDynamicSharedMemorySize, SMEM_BYTES);
    cudaFuncSetAttribute(jacobi_pass,
                         cudaFuncAttributeMaxDynamicSharedMemorySize, SMEM_BYTES);

    dim3 grid(TXN, TYN);

    // pass 0 (fused init + 10 steps): (X,Y) -> B
    jacobi_first<<<grid, NTH, SMEM_BYTES>>>(X, Y, B);

    // passes 1..9: odd p: B -> A, even p: A -> B; p=9 ends in A (=d_out)
    for (int p = 1; p < 10; p++) {
        const float* src = (p & 1) ? B : A;
        float*       dst = (p & 1) ? A : B;
        jacobi_pass<<<grid, NTH, SMEM_BYTES>>>(src, dst);
    }
}